// round 17
// baseline (speedup 1.0000x reference)
#include <cuda_runtime.h>
#include <cstdint>

namespace {

constexpr int NTH  = 128;    // thread k owns groups 2k, 2k+1 (states 8k..8k+7)
constexpr int NCTA = 2048;   // each CTA handles 2 data blocks
constexpr int ROWS = 1024;

__device__ __forceinline__ float costf(const float4 cb, float cn, const float4 x) {
    return fmaf(cb.w, x.w, fmaf(cb.z, x.z, fmaf(cb.y, x.y, fmaf(cb.x, x.x, cn))));
}
__device__ __forceinline__ float cnrm(const float4 c) {
    return fmaf(c.w, c.w, fmaf(c.z, c.z, fmaf(c.y, c.y, c.x * c.x)));
}
// min-of-4 with index in the 2 mantissa LSBs (validated rel_err 0.0 in R11-R16)
__device__ __forceinline__ float min4_lsb(float a0, float a1, float a2, float a3) {
    float p0 = __uint_as_float((__float_as_uint(a0) & ~3u) | 0u);
    float p1 = __uint_as_float((__float_as_uint(a1) & ~3u) | 1u);
    float p2 = __uint_as_float((__float_as_uint(a2) & ~3u) | 2u);
    float p3 = __uint_as_float((__float_as_uint(a3) & ~3u) | 3u);
    return fminf(fminf(p0, p1), fminf(p2, p3));
}

__global__ __launch_bounds__(NTH, 6)
void viterbi_kernel(const float* __restrict__ array,
                    const float* __restrict__ codebook,
                    float* __restrict__ out,
                    int out_size)
{
    __shared__ float gA[2][256], gB[2][256];     // group-min state (ping-pong)
    __shared__ float4 xsA[64], xsB[64];          // read-only after init
    // bp2[k][w]: word w holds byte (idx&3) for idx=4w..4w+3, idx = step-1.
    // byte: jAa | jAb<<2 | jBa<<4 | jBb<<6.  17-word stride -> conflict-free STS.32
    __shared__ unsigned int bp2[NTH][17];
    __shared__ int   pathA[64], pathB[64];
    __shared__ float redvA[4], redvB[4];
    __shared__ int   rediA[4], rediB[4];

    const int k  = threadIdx.x;                  // 0..127
    const int bA = 2 * blockIdx.x;
    const int bB = bA + 1;
    const int brA = bA >> 6, bcA = bA & 63;
    const int brB = bB >> 6, bcB = bB & 63;

    // ---- load both blocks' 256 elements each, pre-scaled by -2 ----
#pragma unroll
    for (int e = k; e < 256; e += NTH) {
        int r = e >> 4, cc = e & 15;
        float vA = array[(brA * 16 + r) * ROWS + (bcA * 16 + cc)];
        float vB = array[(brB * 16 + r) * ROWS + (bcB * 16 + cc)];
        reinterpret_cast<float*>(xsA)[e] = -2.0f * vA;
        reinterpret_cast<float*>(xsB)[e] = -2.0f * vB;
    }

    // ---- candidate cb rows for groups ga=2k, gb=2k+1: g + 256j ----
    const float4* cb4 = reinterpret_cast<const float4*>(codebook);
    const int ga = 2 * k, gb = 2 * k + 1;
    float4 p0 = __ldg(cb4 + ga + 0),   q0 = __ldg(cb4 + gb + 0);
    float4 p1 = __ldg(cb4 + ga + 256), q1 = __ldg(cb4 + gb + 256);
    float4 p2 = __ldg(cb4 + ga + 512), q2 = __ldg(cb4 + gb + 512);
    float4 p3 = __ldg(cb4 + ga + 768), q3 = __ldg(cb4 + gb + 768);
    float pn0 = cnrm(p0), pn1 = cnrm(p1), pn2 = cnrm(p2), pn3 = cnrm(p3);
    float qn0 = cnrm(q0), qn1 = cnrm(q1), qn2 = cnrm(q2), qn3 = cnrm(q3);

    __syncthreads();

    // ---- G_0 for both groups, both blocks (free initial state) ----
    float mAa, mAb, mBa, mBb;
    unsigned int cw;                             // bp accumulation word (4 steps)
    {
        float4 xA = xsA[0], xB = xsB[0];
        mAa = min4_lsb(costf(p0, pn0, xA), costf(p1, pn1, xA), costf(p2, pn2, xA), costf(p3, pn3, xA));
        mAb = min4_lsb(costf(q0, qn0, xA), costf(q1, qn1, xA), costf(q2, qn2, xA), costf(q3, qn3, xA));
        mBa = min4_lsb(costf(p0, pn0, xB), costf(p1, pn1, xB), costf(p2, pn2, xB), costf(p3, pn3, xB));
        mBb = min4_lsb(costf(q0, qn0, xB), costf(q1, qn1, xB), costf(q2, qn2, xB), costf(q3, qn3, xB));
        cw = (__float_as_uint(mAa) & 3u)        |
             ((__float_as_uint(mAb) & 3u) << 2) |
             ((__float_as_uint(mBa) & 3u) << 4) |
             ((__float_as_uint(mBb) & 3u) << 6);          // idx 0 (step 1), byte 0
        *reinterpret_cast<float2*>(&gA[0][ga]) = make_float2(mAa, mAb);
        *reinterpret_cast<float2*>(&gB[0][ga]) = make_float2(mBa, mBb);
    }

    // ---- prefetch BOTH blocks' cost chains for t=1 ----
    float cAa0, cAa1, cAa2, cAa3, cAb0, cAb1, cAb2, cAb3;
    float cBa0, cBa1, cBa2, cBa3, cBb0, cBb1, cBb2, cBb3;
    {
        float4 xA = xsA[1], xB = xsB[1];
        cAa0 = costf(p0, pn0, xA); cAa1 = costf(p1, pn1, xA);
        cAa2 = costf(p2, pn2, xA); cAa3 = costf(p3, pn3, xA);
        cAb0 = costf(q0, qn0, xA); cAb1 = costf(q1, qn1, xA);
        cAb2 = costf(q2, qn2, xA); cAb3 = costf(q3, qn3, xA);
        cBa0 = costf(p0, pn0, xB); cBa1 = costf(p1, pn1, xB);
        cBa2 = costf(p2, pn2, xB); cBa3 = costf(p3, pn3, xB);
        cBb0 = costf(q0, qn0, xB); cBb1 = costf(q1, qn1, xB);
        cBb2 = costf(q2, qn2, xB); cBb3 = costf(q3, qn3, xB);
    }
    __syncthreads();

    // ---- recursion on G: fully software-pipelined ----
    const int base = k >> 1;
#pragma unroll 4
    for (int t = 1; t <= 62; ++t) {
        const float* gpA = gA[(t + 1) & 1];
        const float* gpB = gB[(t + 1) & 1];
        // 1) issue G loads
        float a0 = gpA[base], a1 = gpA[base + 64], a2 = gpA[base + 128], a3 = gpA[base + 192];
        float b0 = gpB[base], b1 = gpB[base + 64], b2 = gpB[base + 128], b3 = gpB[base + 192];

        // 2) next step's cost chains (latency filler; xs read-only)
        float4 xA = xsA[t + 1], xB = xsB[t + 1];
        float nAa0 = costf(p0, pn0, xA), nAa1 = costf(p1, pn1, xA);
        float nAa2 = costf(p2, pn2, xA), nAa3 = costf(p3, pn3, xA);
        float nAb0 = costf(q0, qn0, xA), nAb1 = costf(q1, qn1, xA);
        float nAb2 = costf(q2, qn2, xA), nAb3 = costf(q3, qn3, xA);
        float nBa0 = costf(p0, pn0, xB), nBa1 = costf(p1, pn1, xB);
        float nBa2 = costf(p2, pn2, xB), nBa3 = costf(p3, pn3, xB);
        float nBb0 = costf(q0, qn0, xB), nBb1 = costf(q1, qn1, xB);
        float nBb2 = costf(q2, qn2, xB), nBb3 = costf(q3, qn3, xB);

        // 3) consume: prefetched chains are ready the moment loads land
        mAa = min4_lsb(a0 + cAa0, a1 + cAa1, a2 + cAa2, a3 + cAa3);
        mAb = min4_lsb(a0 + cAb0, a1 + cAb1, a2 + cAb2, a3 + cAb3);
        mBa = min4_lsb(b0 + cBa0, b1 + cBa1, b2 + cBa2, b3 + cBa3);
        mBb = min4_lsb(b0 + cBb0, b1 + cBb1, b2 + cBb2, b3 + cBb3);

        // 4) bp byte for idx = t (step t+1); const shifts under unroll
        unsigned int byte = (__float_as_uint(mAa) & 3u)        |
                            ((__float_as_uint(mAb) & 3u) << 2) |
                            ((__float_as_uint(mBa) & 3u) << 4) |
                            ((__float_as_uint(mBb) & 3u) << 6);
        cw |= byte << (8 * (t & 3));
        if ((t & 3) == 3) { bp2[k][t >> 2] = cw; cw = 0; }

        // 5) store G
        *reinterpret_cast<float2*>(&gA[t & 1][ga]) = make_float2(mAa, mAb);
        *reinterpret_cast<float2*>(&gB[t & 1][ga]) = make_float2(mBa, mBb);

        // 6) rotate prefetch (SSA renames under unroll; no real MOVs)
        cAa0 = nAa0; cAa1 = nAa1; cAa2 = nAa2; cAa3 = nAa3;
        cAb0 = nAb0; cAb1 = nAb1; cAb2 = nAb2; cAb3 = nAb3;
        cBa0 = nBa0; cBa1 = nBa1; cBa2 = nBa2; cBa3 = nBa3;
        cBb0 = nBb0; cBb1 = nBb1; cBb2 = nBb2; cBb3 = nBb3;

        __syncthreads();
    }
    bp2[k][15] = cw;                             // final partial word (idx 60..62)

    // ---- epilogue: alpha_63[s] = G_62[s>>2] + cost_63(s), running argmin ----
    float bmA, bmB; int biA = 8 * k, biB = 8 * k;
    {
        float4 xA = xsA[63], xB = xsB[63];
        bmA = 0.f; bmB = 0.f;
#pragma unroll
        for (int c = 0; c < 8; ++c) {
            float4 oc = __ldg(cb4 + 8 * k + c);
            float onc = cnrm(oc);
            float gAv = (c < 4) ? mAa : mAb;
            float gBv = (c < 4) ? mBa : mBb;
            float vAc = gAv + costf(oc, onc, xA);
            float vBc = gBv + costf(oc, onc, xB);
            if (c == 0) { bmA = vAc; bmB = vBc; }
            else {
                if (vAc < bmA) { bmA = vAc; biA = 8 * k + c; }
                if (vBc < bmB) { bmB = vBc; biB = 8 * k + c; }
            }
        }
#pragma unroll
        for (int off = 16; off; off >>= 1) {
            float om = __shfl_down_sync(0xffffffffu, bmA, off);
            int   oi = __shfl_down_sync(0xffffffffu, biA, off);
            if (om < bmA || (om == bmA && oi < biA)) { bmA = om; biA = oi; }
            float pm = __shfl_down_sync(0xffffffffu, bmB, off);
            int   pi = __shfl_down_sync(0xffffffffu, biB, off);
            if (pm < bmB || (pm == bmB && pi < biB)) { bmB = pm; biB = pi; }
        }
        if ((k & 31) == 0) {
            redvA[k >> 5] = bmA; rediA[k >> 5] = biA;
            redvB[k >> 5] = bmB; rediB[k >> 5] = biB;
        }
    }
    __syncthreads();

    // ---- backtrack: thread 0 does A, thread 32 does B ----
    if (k == 0) {
        float m = redvA[0]; int s = rediA[0];
#pragma unroll
        for (int w = 1; w < 4; ++w)
            if (redvA[w] < m || (redvA[w] == m && rediA[w] < s)) { m = redvA[w]; s = rediA[w]; }
        pathA[63] = s;
        for (int t = 63; t >= 1; --t) {
            int g = s >> 2;
            int idx = t - 1;
            int j = (bp2[g >> 1][idx >> 2] >> (8 * (idx & 3) + 2 * (g & 1))) & 3;
            s = g + (j << 8);                    // prev = (s>>2) + j*256
            pathA[t - 1] = s;
        }
    }
    if (k == 32) {
        float m = redvB[0]; int s = rediB[0];
#pragma unroll
        for (int w = 1; w < 4; ++w)
            if (redvB[w] < m || (redvB[w] == m && rediB[w] < s)) { m = redvB[w]; s = rediB[w]; }
        pathB[63] = s;
        for (int t = 63; t >= 1; --t) {
            int g = s >> 2;
            int idx = t - 1;
            int j = (bp2[g >> 1][idx >> 2] >> (8 * (idx & 3) + 4 + 2 * (g & 1))) & 3;
            s = g + (j << 8);
            pathB[t - 1] = s;
        }
    }
    __syncthreads();

    // ---- emit: rec (exact codebook gather) + states, both blocks ----
    {
        int t = k & 63;
        bool isB = k >= 64;
        int s = isB ? pathB[t] : pathA[t];
        int bb = isB ? bB : bA;
        int br = isB ? brB : brA;
        int bc = isB ? bcB : bcA;
        float4 val = __ldg(cb4 + s);
        int row = br * 16 + (t >> 2);
        int col = bc * 16 + ((t & 3) << 2);
        reinterpret_cast<float4*>(out + row * ROWS + col)[0] = val;
        int sidx = ROWS * ROWS + bb * 64 + t;
        if (sidx < out_size) out[sidx] = (float)s;
    }
}

} // namespace

extern "C" void kernel_launch(void* const* d_in, const int* in_sizes, int n_in,
                              void* d_out, int out_size) {
    const float* array    = (const float*)d_in[0];
    const float* codebook = (const float*)d_in[1];
    (void)in_sizes; (void)n_in;
    float* out = (float*)d_out;
    viterbi_kernel<<<NCTA, NTH>>>(array, codebook, out, out_size);
}